// round 1
// baseline (speedup 1.0000x reference)
#include <cuda_runtime.h>
#include <math.h>

#define IMG_H 512
#define IMG_W 512
#define NB    64
#define NPIX  (IMG_H * IMG_W)
#define NPEL  (NPIX * 3)          // elements per image (H*W*3)
#define RBLK  32                  // reduction blocks per image

// Scratch for the layer-0 -> layer-1 intermediate (allocation-free rule:
// __device__ global array). 64*512*512*3 floats = 201 MB.
__device__ float g_scratch[(size_t)NB * NPEL];
__device__ float g_partial[NB * RBLK];
__device__ float g_mean[NB];

// ---------------------------------------------------------------------------
// Per-image mean (only for images whose op at this layer is contrast, id 6).
// Deterministic: fixed partial slots + ordered final sum (no float atomics).
// ---------------------------------------------------------------------------
__global__ void reduce_kernel(const float* __restrict__ in,
                              const int* __restrict__ op_ids, int layer)
{
    int b = blockIdx.y;
    if (op_ids[b * 2 + layer] != 6) return;   // early-exit: no reads at all
    const float* img = in + (size_t)b * NPEL;
    float s = 0.f;
    for (int i = blockIdx.x * 256 + threadIdx.x; i < NPEL; i += RBLK * 256)
        s += img[i];
    __shared__ float sd[256];
    sd[threadIdx.x] = s;
    __syncthreads();
    #pragma unroll
    for (int st = 128; st > 0; st >>= 1) {
        if (threadIdx.x < st) sd[threadIdx.x] += sd[threadIdx.x + st];
        __syncthreads();
    }
    if (threadIdx.x == 0) g_partial[b * RBLK + blockIdx.x] = sd[0];
}

__global__ void finalize_mean(const int* __restrict__ op_ids, int layer)
{
    int b = threadIdx.x;
    if (b >= NB) return;
    if (op_ids[b * 2 + layer] != 6) return;
    float s = 0.f;
    #pragma unroll
    for (int i = 0; i < RBLK; i++) s += g_partial[b * RBLK + i];
    g_mean[b] = s * (1.0f / (float)NPEL);
}

// ---------------------------------------------------------------------------
// Bilinear corner gather matching the JAX reference exactly:
// valid test on the (float) integer coords, clamp-then-gather, FILL=0.5 else.
// ---------------------------------------------------------------------------
__device__ __forceinline__ void gather_acc(const float* __restrict__ img,
                                           float yy, float xx, float w,
                                           float r[3])
{
    bool valid = (xx >= 0.f) && (xx <= (float)(IMG_W - 1)) &&
                 (yy >= 0.f) && (yy <= (float)(IMG_H - 1));
    int xc = (int)fminf(fmaxf(xx, 0.f), (float)(IMG_W - 1));
    int yc = (int)fminf(fmaxf(yy, 0.f), (float)(IMG_H - 1));
    const float* p = img + ((size_t)yc * IMG_W + xc) * 3;
    if (valid) {
        r[0] += w * p[0];
        r[1] += w * p[1];
        r[2] += w * p[2];
    } else {
        float f = w * 0.5f;      // FILL = 0.5, same for all 3 channels
        r[0] += f; r[1] += f; r[2] += f;
    }
}

// ---------------------------------------------------------------------------
// Apply one augmentation layer. One thread = one pixel (3 channels).
// blockIdx.z = image index, so the op switch is warp-uniform.
// ---------------------------------------------------------------------------
__global__ void apply_layer_kernel(const float* __restrict__ in,
                                   float* __restrict__ out,
                                   const int* __restrict__ op_ids,
                                   const int* __restrict__ signs,
                                   int layer)
{
    const int b   = blockIdx.z;
    const int idx = blockIdx.x * blockDim.x + threadIdx.x;   // 0..NPIX-1
    const int y   = idx >> 9;          // W = 512
    const int x   = idx & 511;

    const float* img = in + (size_t)b * NPEL;
    float* o = out + (size_t)b * NPEL + (size_t)idx * 3;

    const int   op = op_ids[b * 2 + layer];
    const float s  = signs[b * 2 + layer] ? 1.0f : -1.0f;   // 2*sign-1

    const float ENH = 1.45f;           // 1 + 0.9*MAG, MAG = 0.5

    float r[3];

    if (op < 5) {
        // ---- affine family: rotate / shear_x / shear_y / trans_x / trans_y
        float a = 1.f, bb = 0.f, tx = 0.f, c = 0.f, d = 1.f, ty = 0.f;
        if (op == 0) {                         // rotate by s*15 deg
            float th = s * 0.2617993877991494f; // 15 * pi/180
            a = cosf(th); bb = sinf(th); c = -bb; d = a;
        } else if (op == 1) {                  // shear_x
            bb = -s * 0.15f;
        } else if (op == 2) {                  // shear_y
            c  = -s * 0.15f;
        } else if (op == 3) {                  // trans_x
            tx = -s * 0.15f * (float)IMG_W;
        } else {                               // trans_y
            ty = -s * 0.15f * (float)IMG_H;
        }
        const float cx = (IMG_W - 1) * 0.5f;
        const float cy = (IMG_H - 1) * 0.5f;
        float xf = (float)x - cx;
        float yf = (float)y - cy;
        float xi = a * xf + bb * yf + tx + cx;
        float yi = c * xf + d  * yf + ty + cy;
        float x0 = floorf(xi), y0 = floorf(yi);
        float wx = xi - x0,    wy = yi - y0;

        r[0] = r[1] = r[2] = 0.f;
        gather_acc(img, y0,       x0,       (1.f - wx) * (1.f - wy), r);
        gather_acc(img, y0,       x0 + 1.f, wx         * (1.f - wy), r);
        gather_acc(img, y0 + 1.f, x0,       (1.f - wx) * wy,         r);
        gather_acc(img, y0 + 1.f, x0 + 1.f, wx         * wy,         r);
        // affine ops are NOT clipped in the reference
    } else {
        const float f = (s > 0.f) ? ENH : (1.0f / ENH);
        const float* p = img + (size_t)idx * 3;
        float v0 = p[0], v1 = p[1], v2 = p[2];

        if (op == 5) {
            // brightness: clip(f * img)
            r[0] = f * v0; r[1] = f * v1; r[2] = f * v2;
        } else if (op == 6) {
            // contrast: clip(mean + f*(img - mean))
            float m = g_mean[b];
            r[0] = m + f * (v0 - m);
            r[1] = m + f * (v1 - m);
            r[2] = m + f * (v2 - m);
        } else {
            // sharpness: clip(smooth + f*(img - smooth)), 3x3 edge-padded
            float sm0 = 0.f, sm1 = 0.f, sm2 = 0.f;
            #pragma unroll
            for (int dy = -1; dy <= 1; dy++) {
                int yy = min(max(y + dy, 0), IMG_H - 1);
                #pragma unroll
                for (int dx = -1; dx <= 1; dx++) {
                    int xx = min(max(x + dx, 0), IMG_W - 1);
                    float k = (dx == 0 && dy == 0) ? (5.0f / 13.0f)
                                                   : (1.0f / 13.0f);
                    const float* q = img + ((size_t)yy * IMG_W + xx) * 3;
                    sm0 += k * q[0]; sm1 += k * q[1]; sm2 += k * q[2];
                }
            }
            r[0] = sm0 + f * (v0 - sm0);
            r[1] = sm1 + f * (v1 - sm1);
            r[2] = sm2 + f * (v2 - sm2);
        }
        r[0] = fminf(fmaxf(r[0], 0.f), 1.f);
        r[1] = fminf(fmaxf(r[1], 0.f), 1.f);
        r[2] = fminf(fmaxf(r[2], 0.f), 1.f);
    }

    o[0] = r[0]; o[1] = r[1]; o[2] = r[2];
}

// ---------------------------------------------------------------------------
extern "C" void kernel_launch(void* const* d_in, const int* in_sizes, int n_in,
                              void* d_out, int out_size)
{
    const float* images = (const float*)d_in[0];
    const int*   op_ids = (const int*)  d_in[1];
    const int*   signs  = (const int*)  d_in[2];
    float*       out    = (float*)d_out;

    float* scratch = nullptr;
    cudaGetSymbolAddress((void**)&scratch, g_scratch);

    dim3 rgrid(RBLK, NB);
    dim3 agrid(NPIX / 256, 1, NB);

    // Layer 0: input -> scratch
    reduce_kernel   <<<rgrid, 256>>>(images, op_ids, 0);
    finalize_mean   <<<1, 64>>>(op_ids, 0);
    apply_layer_kernel<<<agrid, 256>>>(images, scratch, op_ids, signs, 0);

    // Layer 1: scratch -> out
    reduce_kernel   <<<rgrid, 256>>>(scratch, op_ids, 1);
    finalize_mean   <<<1, 64>>>(op_ids, 1);
    apply_layer_kernel<<<agrid, 256>>>(scratch, out, op_ids, signs, 1);
}